// round 1
// baseline (speedup 1.0000x reference)
#include <cuda_runtime.h>
#include <cuda_bf16.h>
#include <cstdint>

// ============================================================================
// QuadraticSplineStack: 3 stacked quadratic splines (128, 64, 32 knots),
// 5000 genes, 4M elements.
//
// Phase 1 (precompute, warp-per-gene): build per-(gene,bin) 32-byte records:
//   { bl, br, w, lh, d=rh-lh, lc, inv_w, pad }
// Phase 2 (eval, thread-per-element): guess bin = floor(x*nb), walk +/-1
// until bl <= x < br, then evaluate the quadratic + logabsdet.
// ============================================================================

#define MAX_GENES 5000
#define NB0 127
#define NB1 63
#define NB2 31
#define REC_PER_GENE (NB0 + NB1 + NB2)   // 221
#define PARAMS_PER_GENE 445

struct __align__(32) Rec {
    float bl, br, w, lh;    // first float4: bin left loc, bin right loc, width, left height
    float d, lc, invw, pad; // second float4: rh-lh, left cdf, 1/w, pad
};

__device__ Rec g_rec[MAX_GENES * REC_PER_GENE];

// ---------------------------------------------------------------------------
// warp helpers
// ---------------------------------------------------------------------------
__device__ __forceinline__ float warp_incl_scan(float v, int lane) {
#pragma unroll
    for (int o = 1; o < 32; o <<= 1) {
        float t = __shfl_up_sync(0xffffffffu, v, o);
        if (lane >= o) v += t;
    }
    return v;
}

__device__ __forceinline__ float warp_sum(float v) {
#pragma unroll
    for (int o = 16; o; o >>= 1) v += __shfl_xor_sync(0xffffffffu, v, o);
    return v;
}

__device__ __forceinline__ float warp_max(float v) {
#pragma unroll
    for (int o = 16; o; o >>= 1) v = fmaxf(v, __shfl_xor_sync(0xffffffffu, v, o));
    return v;
}

// ---------------------------------------------------------------------------
// Precompute kernel: one warp per gene. Builds all 3 transforms' records.
// Shared per warp: sw (widths), sl (incl scan widths), se (heights), sc (incl
// scan cdf terms), each up to 128 floats.
// ---------------------------------------------------------------------------
__global__ void precompute_kernel(const float* __restrict__ unnorm, int nGenes) {
    __shared__ float sbuf[4][512];   // 4 warps/block, 4x128 floats each

    const int warp_in_blk = threadIdx.x >> 5;
    const int lane = threadIdx.x & 31;
    const int g = blockIdx.x * 4 + warp_in_blk;
    if (g >= nGenes) return;

    float* sw = &sbuf[warp_in_blk][0];
    float* sl = &sbuf[warp_in_blk][128];
    float* se = &sbuf[warp_in_blk][256];
    float* sc = &sbuf[warp_in_blk][384];

    const float* row = unnorm + (long)g * PARAMS_PER_GENE;
    Rec* rec = g_rec + (long)g * REC_PER_GENE;

    const int NS[3]  = {128, 64, 32};
    int poff = 0, roff = 0;

#pragma unroll
    for (int t = 0; t < 3; ++t) {
        const int n  = NS[t];
        const int nb = n - 1;
        const float* uh = row + poff;         // n heights
        const float* uw = row + poff + n;     // nb widths
        poff += n + nb;

        // --- softmax widths ---
        float m = -1e30f;
        for (int i = lane; i < nb; i += 32) m = fmaxf(m, uw[i]);
        m = warp_max(m);
        float s = 0.f;
        for (int i = lane; i < nb; i += 32) {
            float e = __expf(uw[i] - m);
            sw[i] = e;
            s += e;
        }
        s = warp_sum(s);
        float invs = 1.0f / s;
        for (int i = lane; i < nb; i += 32) sw[i] *= invs;
        __syncwarp();

        // --- inclusive scan of widths -> sl ---
        float carry = 0.f;
        for (int base = 0; base < nb; base += 32) {
            int i = base + lane;
            float v = (i < nb) ? sw[i] : 0.f;
            float scn = warp_incl_scan(v, lane);
            if (i < nb) sl[i] = scn + carry;
            carry += __shfl_sync(0xffffffffu, scn, 31);
        }
        __syncwarp();

        // --- heights: exp, trapezoid area, normalize ---
        for (int i = lane; i < n; i += 32) se[i] = __expf(uh[i]);
        __syncwarp();
        float a = 0.f;
        for (int i = lane; i < nb; i += 32) a += 0.5f * (se[i] + se[i + 1]) * sw[i];
        a = warp_sum(a);
        float inva = 1.0f / a;
        for (int i = lane; i < n; i += 32) se[i] *= inva;
        __syncwarp();

        // --- inclusive scan of cdf terms -> sc ---
        carry = 0.f;
        for (int base = 0; base < nb; base += 32) {
            int i = base + lane;
            float v = (i < nb) ? 0.5f * (se[i] + se[i + 1]) * sw[i] : 0.f;
            float scn = warp_incl_scan(v, lane);
            if (i < nb) sc[i] = scn + carry;
            carry += __shfl_sync(0xffffffffu, scn, 31);
        }
        __syncwarp();

        // --- emit records ---
        for (int b = lane; b < nb; b += 32) {
            Rec r;
            r.bl   = (b == 0) ? 0.0f : sl[b - 1];
            r.br   = (b == nb - 1) ? 1.0f : sl[b];
            r.w    = sw[b];
            r.lh   = se[b];
            r.d    = se[b + 1] - se[b];
            r.lc   = (b == 0) ? 0.0f : sc[b - 1];
            r.invw = 1.0f / sw[b];
            r.pad  = 0.0f;
            rec[roff + b] = r;
        }
        __syncwarp();
        roff += nb;
    }
}

// ---------------------------------------------------------------------------
// Eval kernel: one thread per element.
// ---------------------------------------------------------------------------
__device__ __forceinline__ float apply_transform(const Rec* __restrict__ recs, int nb,
                                                 float v, float& lad) {
    int b = (int)(v * (float)nb);
    b = (b < 0) ? 0 : ((b > nb - 1) ? nb - 1 : b);

    const float4* p = reinterpret_cast<const float4*>(recs + b);
    float4 r0 = __ldg(p);                 // {bl, br, w, lh}
    // walk left
    while (v < r0.x && b > 0) {
        --b;
        r0 = __ldg(reinterpret_cast<const float4*>(recs + b));
    }
    // walk right
    while (v >= r0.y && b < nb - 1) {
        ++b;
        r0 = __ldg(reinterpret_cast<const float4*>(recs + b));
    }
    float4 r1 = __ldg(reinterpret_cast<const float4*>(recs + b) + 1);  // {d, lc, invw, pad}

    float alpha = (v - r0.x) * r1.z;
    float o = fmaf(fmaf(0.5f * r1.x * r0.z, alpha, r0.w * r0.z), alpha, r1.y);
    lad += __logf(fmaf(alpha, r1.x, r0.w));
    return fminf(fmaxf(o, 0.0f), 1.0f);
}

__global__ void __launch_bounds__(256) spline_eval_kernel(
    const float* __restrict__ x,
    const int* __restrict__ gix,
    float* __restrict__ out,
    float* __restrict__ lad_out,
    int N)
{
    int i = blockIdx.x * blockDim.x + threadIdx.x;
    if (i >= N) return;

    float v = x[i];
    int g = gix[i];
    const Rec* base = g_rec + (long)g * REC_PER_GENE;

    float lad = 0.f;
    v = apply_transform(base,              NB0, v, lad);
    v = apply_transform(base + NB0,        NB1, v, lad);
    v = apply_transform(base + NB0 + NB1,  NB2, v, lad);

    out[i]     = v;
    lad_out[i] = lad;
}

// ---------------------------------------------------------------------------
// launch
// ---------------------------------------------------------------------------
extern "C" void kernel_launch(void* const* d_in, const int* in_sizes, int n_in,
                              void* d_out, int out_size) {
    const float* x      = (const float*)d_in[0];
    const int*   gix    = (const int*)d_in[1];
    const float* unnorm = (const float*)d_in[2];

    int N = in_sizes[0];
    int nGenes = in_sizes[2] / PARAMS_PER_GENE;
    if (nGenes > MAX_GENES) nGenes = MAX_GENES;

    float* out = (float*)d_out;
    float* lad = out + N;

    precompute_kernel<<<(nGenes + 3) / 4, 128>>>(unnorm, nGenes);
    spline_eval_kernel<<<(N + 255) / 256, 256>>>(x, gix, out, lad, N);
}

// round 2
// speedup vs baseline: 1.1889x; 1.1889x over previous
#include <cuda_runtime.h>
#include <cuda_bf16.h>
#include <cstdint>

// ============================================================================
// QuadraticSplineStack: 3 stacked quadratic splines (128, 64, 32 knots),
// 5000 genes, 4M elements.
//
// R2 design: one 16-byte scattered load per transform in the common case.
//  - Cell table (M = 2*nb uniform cells per transform): cell c holds the FULL
//    packed record of the bin containing the cell center. Probe = 1 LDG.128.
//  - Miss (alpha outside [0,1)): direction-locked walk over a bin-indexed
//    table; bin index is embedded in the record.
//  - Record (16B): bl as u24 fixed-point (+8 bit bin idx), invw u16 fixed,
//    lh u16 fixed, d f32, lc f32.  out = lc + (x-bl)*(lh + 0.5*d*alpha)
//    needs no reciprocal since w*alpha == (x - bl).
// ============================================================================

#define MAX_GENES 5000
#define PARAMS_PER_GENE 445

// per-transform geometry
#define NBINS0 127
#define NBINS1 63
#define NBINS2 31
#define CELLS_PER_GENE (2*NBINS0 + 2*NBINS1 + 2*NBINS2)   // 442
#define BINS_PER_GENE  (NBINS0 + NBINS1 + NBINS2)         // 221

struct __align__(16) Rec {
    unsigned blq;      // bits[31:8] = bl * 2^32 (top 24 bits), bits[7:0] = bin idx
    unsigned invw_lh;  // low16: invw * 16384/nb ; high16: lh * 16384
    float    d;        // rh - lh
    float    lc;       // left cdf
};

__device__ Rec g_cell[MAX_GENES * CELLS_PER_GENE];
__device__ Rec g_bin [MAX_GENES * BINS_PER_GENE];

// ---------------------------------------------------------------------------
// warp helpers
// ---------------------------------------------------------------------------
__device__ __forceinline__ float warp_incl_scan(float v, int lane) {
#pragma unroll
    for (int o = 1; o < 32; o <<= 1) {
        float t = __shfl_up_sync(0xffffffffu, v, o);
        if (lane >= o) v += t;
    }
    return v;
}
__device__ __forceinline__ float warp_sum(float v) {
#pragma unroll
    for (int o = 16; o; o >>= 1) v += __shfl_xor_sync(0xffffffffu, v, o);
    return v;
}
__device__ __forceinline__ float warp_max(float v) {
#pragma unroll
    for (int o = 16; o; o >>= 1) v = fmaxf(v, __shfl_xor_sync(0xffffffffu, v, o));
    return v;
}

// ---------------------------------------------------------------------------
// record builder (reads per-transform tables from shared memory)
// ---------------------------------------------------------------------------
__device__ __forceinline__ Rec make_rec(int b, const float* sw, const float* sl,
                                        const float* se, const float* sc,
                                        float invw_scale) {
    float bl = b ? sl[b - 1] : 0.f;
    float w  = sw[b];
    float lh = se[b];
    Rec r;
    unsigned q = (unsigned)fminf(rintf(bl * 4294967296.f), 4294967040.f);
    r.blq = (q & 0xFFFFFF00u) | (unsigned)b;
    unsigned iq = (unsigned)fminf(rintf((1.f / w) * invw_scale), 65535.f);
    unsigned lq = (unsigned)fminf(rintf(lh * 16384.f), 65535.f);
    r.invw_lh = iq | (lq << 16);
    r.d  = se[b + 1] - lh;
    r.lc = b ? sc[b - 1] : 0.f;
    return r;
}

// ---------------------------------------------------------------------------
// Precompute: one warp per (gene, transform).
// ---------------------------------------------------------------------------
__global__ void precompute_kernel(const float* __restrict__ unnorm, int nGenes) {
    __shared__ float sbuf[4][512];

    const int wib  = threadIdx.x >> 5;
    const int lane = threadIdx.x & 31;
    const int wid  = blockIdx.x * 4 + wib;
    const int g    = wid / 3;
    const int t    = wid - g * 3;
    if (g >= nGenes) return;

    const int NS[3]   = {128, 64, 32};
    const int POFF[3] = {0, 255, 382};
    const int COFF[3] = {0, 2 * NBINS0, 2 * NBINS0 + 2 * NBINS1};
    const int BOFF[3] = {0, NBINS0, NBINS0 + NBINS1};

    const int n  = NS[t];
    const int nb = n - 1;
    const int M  = 2 * nb;
    const float invw_scale = 16384.f / (float)nb;

    const float* uh = unnorm + (long)g * PARAMS_PER_GENE + POFF[t];
    const float* uw = uh + n;

    float* sw = sbuf[wib];
    float* sl = sw + 128;
    float* se = sl + 128;
    float* sc = se + 128;

    // softmax widths
    float m = -1e30f;
    for (int i = lane; i < nb; i += 32) m = fmaxf(m, uw[i]);
    m = warp_max(m);
    float s = 0.f;
    for (int i = lane; i < nb; i += 32) {
        float e = __expf(uw[i] - m);
        sw[i] = e;
        s += e;
    }
    s = warp_sum(s);
    float invs = 1.0f / s;
    for (int i = lane; i < nb; i += 32) sw[i] *= invs;
    __syncwarp();

    // inclusive scan of widths -> sl
    float carry = 0.f;
    for (int base = 0; base < nb; base += 32) {
        int i = base + lane;
        float v = (i < nb) ? sw[i] : 0.f;
        float scn = warp_incl_scan(v, lane);
        if (i < nb) sl[i] = scn + carry;
        carry += __shfl_sync(0xffffffffu, scn, 31);
    }
    __syncwarp();

    // heights
    for (int i = lane; i < n; i += 32) se[i] = __expf(uh[i]);
    __syncwarp();
    float a = 0.f;
    for (int i = lane; i < nb; i += 32) a += 0.5f * (se[i] + se[i + 1]) * sw[i];
    a = warp_sum(a);
    float inva = 1.0f / a;
    for (int i = lane; i < n; i += 32) se[i] *= inva;
    __syncwarp();

    // inclusive scan of cdf terms -> sc
    carry = 0.f;
    for (int base = 0; base < nb; base += 32) {
        int i = base + lane;
        float v = (i < nb) ? 0.5f * (se[i] + se[i + 1]) * sw[i] : 0.f;
        float scn = warp_incl_scan(v, lane);
        if (i < nb) sc[i] = scn + carry;
        carry += __shfl_sync(0xffffffffu, scn, 31);
    }
    __syncwarp();

    // emit bin-indexed records
    Rec* brec = g_bin  + (long)g * BINS_PER_GENE  + BOFF[t];
    Rec* crec = g_cell + (long)g * CELLS_PER_GENE + COFF[t];
    for (int b = lane; b < nb; b += 32)
        brec[b] = make_rec(b, sw, sl, se, sc, invw_scale);

    // emit cell-indexed records (bin containing cell center)
    const float invM = 1.0f / (float)M;
    for (int c = lane; c < M; c += 32) {
        float center = ((float)c + 0.5f) * invM;
        int lo = 0, hi = nb;
        while (lo < hi) {
            int mid = (lo + hi) >> 1;
            if (sl[mid] <= center) lo = mid + 1; else hi = mid;
        }
        int b = (lo < nb - 1) ? lo : (nb - 1);
        crec[c] = make_rec(b, sw, sl, se, sc, invw_scale);
    }
}

// ---------------------------------------------------------------------------
// Eval: one thread per element, one 16B probe per transform (common case).
// ---------------------------------------------------------------------------
template<int NB>
__device__ __forceinline__ float apply_t(const Rec* __restrict__ cell,
                                         const Rec* __restrict__ bin,
                                         float v, float& lad) {
    constexpr int   M       = 2 * NB;
    constexpr float INVW_SC = (float)NB / 16384.f;
    constexpr float LH_SC   = 1.f / 16384.f;
    constexpr float BL_SC   = 2.3283064365386963e-10f;  // 2^-32

    int c = (int)(v * (float)M);
    c = (c < 0) ? 0 : ((c > M - 1) ? (M - 1) : c);

    uint4 u = __ldg(reinterpret_cast<const uint4*>(cell + c));
    int   b     = (int)(u.x & 0xFFu);
    float bl    = (float)(u.x & 0xFFFFFF00u) * BL_SC;
    float invw  = (float)(u.y & 0xFFFFu) * INVW_SC;
    float alpha = (v - bl) * invw;

    if (alpha < 0.f) {
        while (alpha < 0.f && b > 0) {
            --b;
            u = __ldg(reinterpret_cast<const uint4*>(bin + b));
            bl    = (float)(u.x & 0xFFFFFF00u) * BL_SC;
            invw  = (float)(u.y & 0xFFFFu) * INVW_SC;
            alpha = (v - bl) * invw;
        }
    } else if (alpha >= 1.f) {
        while (alpha >= 1.f && b < NB - 1) {
            ++b;
            u = __ldg(reinterpret_cast<const uint4*>(bin + b));
            bl    = (float)(u.x & 0xFFFFFF00u) * BL_SC;
            invw  = (float)(u.y & 0xFFFFu) * INVW_SC;
            alpha = (v - bl) * invw;
        }
    }

    float lh = (float)(u.y >> 16) * LH_SC;
    float d  = __uint_as_float(u.z);
    float lc = __uint_as_float(u.w);

    lad += __logf(fmaf(d, alpha, lh));
    float out = fmaf(v - bl, fmaf(0.5f * d, alpha, lh), lc);
    return fminf(fmaxf(out, 0.f), 1.f);
}

__global__ void __launch_bounds__(256) spline_eval_kernel(
    const float* __restrict__ x,
    const int* __restrict__ gix,
    float* __restrict__ out,
    float* __restrict__ lad_out,
    int N)
{
    int i = blockIdx.x * blockDim.x + threadIdx.x;
    if (i >= N) return;

    float v = x[i];
    int g = gix[i];
    const Rec* cb = g_cell + (long)g * CELLS_PER_GENE;
    const Rec* bb = g_bin  + (long)g * BINS_PER_GENE;

    float lad = 0.f;
    v = apply_t<NBINS0>(cb,                         bb,                   v, lad);
    v = apply_t<NBINS1>(cb + 2 * NBINS0,            bb + NBINS0,          v, lad);
    v = apply_t<NBINS2>(cb + 2 * (NBINS0 + NBINS1), bb + NBINS0 + NBINS1, v, lad);

    out[i]     = v;
    lad_out[i] = lad;
}

// ---------------------------------------------------------------------------
// launch
// ---------------------------------------------------------------------------
extern "C" void kernel_launch(void* const* d_in, const int* in_sizes, int n_in,
                              void* d_out, int out_size) {
    const float* x      = (const float*)d_in[0];
    const int*   gix    = (const int*)d_in[1];
    const float* unnorm = (const float*)d_in[2];

    int N = in_sizes[0];
    int nGenes = in_sizes[2] / PARAMS_PER_GENE;
    if (nGenes > MAX_GENES) nGenes = MAX_GENES;

    float* out = (float*)d_out;
    float* lad = out + N;

    int nWarps = nGenes * 3;
    precompute_kernel<<<(nWarps + 3) / 4, 128>>>(unnorm, nGenes);
    spline_eval_kernel<<<(N + 255) / 256, 256>>>(x, gix, out, lad, N);
}

// round 3
// speedup vs baseline: 1.4900x; 1.2533x over previous
#include <cuda_runtime.h>
#include <cuda_bf16.h>
#include <cstdint>

// ============================================================================
// QuadraticSplineStack: 3 stacked quadratic splines (128, 64, 32 knots),
// 5000 genes, 4M elements.
//
// R3: single cell-indexed table (no bin table). M = 2*nb uniform cells per
// transform; cell c holds the packed record of the bin containing its center.
// Probe = 1 LDG.128; miss (alpha outside [0,1)) walks +/-1 in CELL space.
// Streaming data uses evict-first hints so the 35MB table stays L2-resident.
//
// Record (16B): { bl f32, invw u16 | lh u16, d f32, lc f32 }
//   alpha = (x-bl)*invw;  out = lc + (x-bl)*(lh + 0.5*d*alpha)  (w*alpha == x-bl)
//   lad  += log(lh + d*alpha)
// ============================================================================

#define MAX_GENES 5000
#define PARAMS_PER_GENE 445

#define NBINS0 127
#define NBINS1 63
#define NBINS2 31
#define CELLS_PER_GENE (2*NBINS0 + 2*NBINS1 + 2*NBINS2)   // 442

struct __align__(16) Rec {
    float    bl;       // bin left location (exact f32)
    unsigned invw_lh;  // low16: invw * 16384/nb ; high16: lh * 16384
    float    d;        // rh - lh
    float    lc;       // left cdf
};

__device__ Rec g_cell[MAX_GENES * CELLS_PER_GENE];

// ---------------------------------------------------------------------------
// warp helpers
// ---------------------------------------------------------------------------
__device__ __forceinline__ float warp_incl_scan(float v, int lane) {
#pragma unroll
    for (int o = 1; o < 32; o <<= 1) {
        float t = __shfl_up_sync(0xffffffffu, v, o);
        if (lane >= o) v += t;
    }
    return v;
}
__device__ __forceinline__ float warp_sum(float v) {
#pragma unroll
    for (int o = 16; o; o >>= 1) v += __shfl_xor_sync(0xffffffffu, v, o);
    return v;
}
__device__ __forceinline__ float warp_max(float v) {
#pragma unroll
    for (int o = 16; o; o >>= 1) v = fmaxf(v, __shfl_xor_sync(0xffffffffu, v, o));
    return v;
}

// ---------------------------------------------------------------------------
// Precompute: one warp per (gene, transform). 8 warps / 256-thread block.
// Cell table filled by per-bin range cover (gap-free: adjacent bins use the
// identical float boundary in the identical formula).
// ---------------------------------------------------------------------------
__global__ void __launch_bounds__(256) precompute_kernel(const float* __restrict__ unnorm,
                                                         int nGenes) {
    __shared__ float sbuf[8][512];

    const int wib  = threadIdx.x >> 5;
    const int lane = threadIdx.x & 31;
    const int wid  = blockIdx.x * 8 + wib;
    const int g    = wid / 3;
    const int t    = wid - g * 3;
    if (g >= nGenes) return;

    const int NS[3]   = {128, 64, 32};
    const int POFF[3] = {0, 255, 382};
    const int COFF[3] = {0, 2 * NBINS0, 2 * NBINS0 + 2 * NBINS1};

    const int n  = NS[t];
    const int nb = n - 1;
    const int M  = 2 * nb;
    const float invw_scale = 16384.f / (float)nb;

    const float* uh = unnorm + (long)g * PARAMS_PER_GENE + POFF[t];
    const float* uw = uh + n;

    float* sw = sbuf[wib];
    float* sl = sw + 128;
    float* se = sl + 128;
    float* sc = se + 128;

    // softmax widths
    float m = -1e30f;
    for (int i = lane; i < nb; i += 32) m = fmaxf(m, uw[i]);
    m = warp_max(m);
    float s = 0.f;
    for (int i = lane; i < nb; i += 32) {
        float e = __expf(uw[i] - m);
        sw[i] = e;
        s += e;
    }
    s = warp_sum(s);
    float invs = 1.0f / s;
    for (int i = lane; i < nb; i += 32) sw[i] *= invs;
    __syncwarp();

    // inclusive scan of widths -> sl
    float carry = 0.f;
    for (int base = 0; base < nb; base += 32) {
        int i = base + lane;
        float v = (i < nb) ? sw[i] : 0.f;
        float scn = warp_incl_scan(v, lane);
        if (i < nb) sl[i] = scn + carry;
        carry += __shfl_sync(0xffffffffu, scn, 31);
    }
    __syncwarp();

    // heights: exp, trapezoid area, normalize
    for (int i = lane; i < n; i += 32) se[i] = __expf(uh[i]);
    __syncwarp();
    float a = 0.f;
    for (int i = lane; i < nb; i += 32) a += 0.5f * (se[i] + se[i + 1]) * sw[i];
    a = warp_sum(a);
    float inva = 1.0f / a;
    for (int i = lane; i < n; i += 32) se[i] *= inva;
    __syncwarp();

    // inclusive scan of cdf terms -> sc
    carry = 0.f;
    for (int base = 0; base < nb; base += 32) {
        int i = base + lane;
        float v = (i < nb) ? 0.5f * (se[i] + se[i + 1]) * sw[i] : 0.f;
        float scn = warp_incl_scan(v, lane);
        if (i < nb) sc[i] = scn + carry;
        carry += __shfl_sync(0xffffffffu, scn, 31);
    }
    __syncwarp();

    // emit cell records: bin b covers cells [f(bl), f(br)), f(t) = ceil(t*M - 0.5)
    Rec* crec = g_cell + (long)g * CELLS_PER_GENE + COFF[t];
    const float Mf = (float)M;
    for (int b = lane; b < nb; b += 32) {
        float blv = b ? sl[b - 1] : 0.f;
        float lh  = se[b];

        Rec r;
        r.bl = blv;
        unsigned iq = (unsigned)fminf(rintf((1.f / sw[b]) * invw_scale), 65535.f);
        unsigned lq = (unsigned)fminf(rintf(lh * 16384.f), 65535.f);
        r.invw_lh = iq | (lq << 16);
        r.d  = se[b + 1] - lh;
        r.lc = b ? sc[b - 1] : 0.f;

        int c0 = b ? (int)ceilf(blv * Mf - 0.5f) : 0;
        int c1 = (b == nb - 1) ? M : (int)ceilf(sl[b] * Mf - 0.5f);
        c0 = (c0 < 0) ? 0 : c0;
        c1 = (c1 > M) ? M : c1;
        for (int c = c0; c < c1; ++c) crec[c] = r;
    }
}

// ---------------------------------------------------------------------------
// Eval: 2 elements per thread, one 16B probe per transform (common case).
// ---------------------------------------------------------------------------
template<int NB>
__device__ __forceinline__ float apply_t(const Rec* __restrict__ cell,
                                         float v, float& lad) {
    constexpr int   M       = 2 * NB;
    constexpr float INVW_SC = (float)NB / 16384.f;
    constexpr float LH_SC   = 1.f / 16384.f;

    int c = (int)(v * (float)M);
    c = (c < 0) ? 0 : ((c > M - 1) ? (M - 1) : c);

    uint4 u = __ldg(reinterpret_cast<const uint4*>(cell + c));
    float bl    = __uint_as_float(u.x);
    float invw  = (float)(u.y & 0xFFFFu) * INVW_SC;
    float alpha = (v - bl) * invw;

    if (alpha < 0.f) {
        do {
            --c;
            u = __ldg(reinterpret_cast<const uint4*>(cell + c));
            bl    = __uint_as_float(u.x);
            invw  = (float)(u.y & 0xFFFFu) * INVW_SC;
            alpha = (v - bl) * invw;
        } while (alpha < 0.f && c > 0);
    } else if (alpha >= 1.f) {
        do {
            ++c;
            u = __ldg(reinterpret_cast<const uint4*>(cell + c));
            bl    = __uint_as_float(u.x);
            invw  = (float)(u.y & 0xFFFFu) * INVW_SC;
            alpha = (v - bl) * invw;
        } while (alpha >= 1.f && c < M - 1);
    }

    float lh = (float)(u.y >> 16) * LH_SC;
    float d  = __uint_as_float(u.z);
    float lc = __uint_as_float(u.w);

    lad += __logf(fmaf(d, alpha, lh));
    float out = fmaf(v - bl, fmaf(0.5f * d, alpha, lh), lc);
    return fminf(fmaxf(out, 0.f), 1.f);
}

__device__ __forceinline__ float eval_one(float v, int g, float& lad) {
    const Rec* cb = g_cell + (long)g * CELLS_PER_GENE;
    v = apply_t<NBINS0>(cb, v, lad);
    v = apply_t<NBINS1>(cb + 2 * NBINS0, v, lad);
    v = apply_t<NBINS2>(cb + 2 * (NBINS0 + NBINS1), v, lad);
    return v;
}

__global__ void __launch_bounds__(256) spline_eval_kernel(
    const float* __restrict__ x,
    const int* __restrict__ gix,
    float* __restrict__ out,
    float* __restrict__ lad_out,
    int N)
{
    long t = (long)blockIdx.x * blockDim.x + threadIdx.x;
    long base = t * 2;
    if (base >= N) return;

    if (base + 1 < N) {
        float2 xv = __ldcs(reinterpret_cast<const float2*>(x) + t);
        int2   gv = __ldcs(reinterpret_cast<const int2*>(gix) + t);

        float lad0 = 0.f, lad1 = 0.f;
        float v0 = xv.x, v1 = xv.y;
        const Rec* cb0 = g_cell + (long)gv.x * CELLS_PER_GENE;
        const Rec* cb1 = g_cell + (long)gv.y * CELLS_PER_GENE;

        v0 = apply_t<NBINS0>(cb0, v0, lad0);
        v1 = apply_t<NBINS0>(cb1, v1, lad1);
        v0 = apply_t<NBINS1>(cb0 + 2 * NBINS0, v0, lad0);
        v1 = apply_t<NBINS1>(cb1 + 2 * NBINS0, v1, lad1);
        v0 = apply_t<NBINS2>(cb0 + 2 * (NBINS0 + NBINS1), v0, lad0);
        v1 = apply_t<NBINS2>(cb1 + 2 * (NBINS0 + NBINS1), v1, lad1);

        __stcs(reinterpret_cast<float2*>(out) + t,     make_float2(v0, v1));
        __stcs(reinterpret_cast<float2*>(lad_out) + t, make_float2(lad0, lad1));
    } else {
        float v = __ldcs(x + base);
        int   g = __ldcs(gix + base);
        float lad = 0.f;
        v = eval_one(v, g, lad);
        __stcs(out + base, v);
        __stcs(lad_out + base, lad);
    }
}

// ---------------------------------------------------------------------------
// launch
// ---------------------------------------------------------------------------
extern "C" void kernel_launch(void* const* d_in, const int* in_sizes, int n_in,
                              void* d_out, int out_size) {
    const float* x      = (const float*)d_in[0];
    const int*   gix    = (const int*)d_in[1];
    const float* unnorm = (const float*)d_in[2];

    int N = in_sizes[0];
    int nGenes = in_sizes[2] / PARAMS_PER_GENE;
    if (nGenes > MAX_GENES) nGenes = MAX_GENES;

    float* out = (float*)d_out;
    float* lad = out + N;

    int nWarps = nGenes * 3;
    precompute_kernel<<<(nWarps + 7) / 8, 256>>>(unnorm, nGenes);

    int nThreads = (N + 1) / 2;
    spline_eval_kernel<<<(nThreads + 255) / 256, 256>>>(x, gix, out, lad, N);
}